// round 5
// baseline (speedup 1.0000x reference)
#include <cuda_runtime.h>
#include <math.h>

// Problem constants
#define PB     32
#define PN     325
#define PK     20
#define S_IN   12
#define S_OUT  12
#define PC     10
#define H48    48            // 4*S_OUT hidden dim
#define BN     (PB * PN)     // 10400 nodes
#define OUT_DATA_ELEMS (BN * PC * S_OUT)   // 1,248,000

// ---------------- scratch (no allocation allowed) ----------------
__device__ float  g_wh [BN * S_OUT];   // wh per node (12)
__device__ float  g_hxb[BN * H48];     // hx + a1_b per node (48)
__device__ float  g_hy [BN * H48];     // hy per node (48)
__device__ double g_acc[3];            // 0: cluster-loss sum, 1: dist sum, 2: wh sum

__device__ __forceinline__ float leaky(float x) { return x >= 0.f ? x : 0.5f * x; }

// ---------------- kernel 0: zero accumulators ----------------
__global__ void k_init() {
    if (threadIdx.x < 3) g_acc[threadIdx.x] = 0.0;
}

// ---------------- kernel 1: per-node precompute ----------------
// wh = leaky(x @ w_W + w_b); hxb = wh @ a1_W[:12] + a1_b; hy = wh @ a1_W[12:]
__global__ void k_pre(const float* __restrict__ in,
                      const float* __restrict__ wW,  const float* __restrict__ wb,
                      const float* __restrict__ a1W, const float* __restrict__ a1b)
{
    __shared__ float s_wW[S_IN * S_OUT];       // 144
    __shared__ float s_wb[S_OUT];              // 12
    __shared__ float s_a1W[2 * S_OUT * H48];   // 1152
    __shared__ float s_a1b[H48];               // 48
    __shared__ double s_red[8];

    for (int i = threadIdx.x; i < S_IN * S_OUT;     i += blockDim.x) s_wW[i]  = wW[i];
    for (int i = threadIdx.x; i < S_OUT;            i += blockDim.x) s_wb[i]  = wb[i];
    for (int i = threadIdx.x; i < 2 * S_OUT * H48;  i += blockDim.x) s_a1W[i] = a1W[i];
    for (int i = threadIdx.x; i < H48;              i += blockDim.x) s_a1b[i] = a1b[i];
    __syncthreads();

    int node = blockIdx.x * blockDim.x + threadIdx.x;
    float whsum = 0.f;
    if (node < BN) {
        float x[S_IN];
        #pragma unroll
        for (int i = 0; i < S_IN; i++) x[i] = in[node * S_IN + i];

        float wh[S_OUT];
        #pragma unroll
        for (int j = 0; j < S_OUT; j++) {
            float a = s_wb[j];
            #pragma unroll
            for (int i = 0; i < S_IN; i++) a = fmaf(x[i], s_wW[i * S_OUT + j], a);
            wh[j] = leaky(a);
            whsum += wh[j];
            g_wh[node * S_OUT + j] = wh[j];
        }
        #pragma unroll
        for (int d = 0; d < H48; d++) {
            float hx = s_a1b[d];
            float hy = 0.f;
            #pragma unroll
            for (int j = 0; j < S_OUT; j++) {
                hx = fmaf(wh[j], s_a1W[j * H48 + d], hx);
                hy = fmaf(wh[j], s_a1W[(S_OUT + j) * H48 + d], hy);
            }
            g_hxb[node * H48 + d] = hx;
            g_hy [node * H48 + d] = hy;
        }
    }

    // block-reduce whsum -> double atomic
    #pragma unroll
    for (int o = 16; o > 0; o >>= 1) whsum += __shfl_down_sync(0xffffffffu, whsum, o);
    int warp = threadIdx.x >> 5, lane = threadIdx.x & 31;
    if (lane == 0) s_red[warp] = (double)whsum;
    __syncthreads();
    if (threadIdx.x == 0) {
        double t = 0.0;
        int nw = (blockDim.x + 31) >> 5;
        for (int w = 0; w < nw; w++) t += s_red[w];
        atomicAdd(&g_acc[2], t);
    }
}

// ---------------- kernel 2: per-node attention + output + pair losses ----------------
__global__ void __launch_bounds__(256, 8)
k_main(const int* __restrict__ idx,
       const float* __restrict__ a2W, const float* __restrict__ a2b,
       float* __restrict__ out)
{
    const int node = blockIdx.x;         // 0..BN-1
    const int b    = node / PN;
    const int tid  = threadIdx.x;        // 256 threads

    __shared__ float s_hxa[H48];             // hx + a1_b for this node
    __shared__ float s_hy [PK][H48];         // gathered hy (20 x 48)
    __shared__ float s_w2 [H48 * PC];        // a2_W (480)
    __shared__ float s_b2 [PC];
    __shared__ float s_whk[PK][S_OUT];       // gathered wh (20 x 12)
    __shared__ float s_am [PK][PC];          // attention -> softmaxed mask
    __shared__ float s_inv[PK];              // 1/(||wh_k||+1e-8)
    __shared__ int   s_j  [PK];
    __shared__ double s_red[16];

    if (tid < PK) s_j[tid] = idx[node * PK + tid];
    for (int i = tid; i < H48 * PC; i += blockDim.x) s_w2[i] = a2W[i];
    if (tid < PC) s_b2[tid] = a2b[tid];
    for (int i = tid; i < H48; i += blockDim.x) s_hxa[i] = g_hxb[node * H48 + i];
    __syncthreads();

    // gather neighbor hy and wh
    for (int i = tid; i < PK * H48; i += blockDim.x) {
        int k = i / H48, d = i % H48;
        s_hy[k][d] = g_hy[((size_t)(b * PN + s_j[k])) * H48 + d];
    }
    for (int i = tid; i < PK * S_OUT; i += blockDim.x) {
        int k = i / S_OUT, s = i % S_OUT;
        s_whk[k][s] = g_wh[((size_t)(b * PN + s_j[k])) * S_OUT + s];
    }
    __syncthreads();

    // attention logits: thread per (k, c)
    if (tid < PK * PC) {
        int k = tid / PC, c = tid % PC;
        float acc = s_b2[c];
        #pragma unroll
        for (int d = 0; d < H48; d++) {
            float h = leaky(s_hxa[d] + s_hy[k][d]);
            acc = fmaf(h, s_w2[d * PC + c], acc);
        }
        s_am[k][c] = leaky(acc);
    }
    __syncthreads();

    // softmax over C per k, and inv-norm per k
    if (tid < PK) {
        int k = tid;
        float m = s_am[k][0];
        #pragma unroll
        for (int c = 1; c < PC; c++) m = fmaxf(m, s_am[k][c]);
        float e[PC]; float sum = 0.f;
        #pragma unroll
        for (int c = 0; c < PC; c++) { e[c] = __expf(s_am[k][c] - m); sum += e[c]; }
        float invs = 1.f / sum;
        #pragma unroll
        for (int c = 0; c < PC; c++) s_am[k][c] = e[c] * invs;

        float n2 = 0.f;
        #pragma unroll
        for (int s = 0; s < S_OUT; s++) n2 = fmaf(s_whk[k][s], s_whk[k][s], n2);
        s_inv[k] = 1.f / (sqrtf(n2) + 1e-8f);
    }
    __syncthreads();

    // output_data[b,n,c,s] = sum_k am[k,c] * wh_topk[k,s]
    if (tid < PC * S_OUT) {
        int c = tid / S_OUT, s = tid % S_OUT;
        float acc = 0.f;
        #pragma unroll
        for (int k = 0; k < PK; k++) acc = fmaf(s_am[k][c], s_whk[k][s], acc);
        out[(size_t)node * (PC * S_OUT) + c * S_OUT + s] = acc;
    }

    // K x K pair phase: dist (all pairs, incl. diag) and cluster loss (off-diag)
    float clsum = 0.f, dsum = 0.f;
    for (int p = tid; p < PK * PK; p += blockDim.x) {
        int k = p / PK, l = p % PK;
        float dot = 0.f;
        #pragma unroll
        for (int s = 0; s < S_OUT; s++) dot = fmaf(s_whk[k][s], s_whk[l][s], dot);
        float dist = dot * s_inv[k] * s_inv[l];
        dsum += dist;
        if (k != l) {
            float prob = 0.f;
            #pragma unroll
            for (int c = 0; c < PC; c++) prob = fmaf(s_am[k][c], s_am[l][c], prob);
            prob = fminf(fmaxf(prob, 1e-4f), 1.f - 1e-4f);
            float logp = __logf(prob);
            // cl = -(same*logp - diff*logp): same -> -logp, diff -> +logp
            clsum += (dist >= 0.5f) ? -logp : logp;
        }
    }

    // block-reduce clsum, dsum -> double atomics
    #pragma unroll
    for (int o = 16; o > 0; o >>= 1) {
        clsum += __shfl_down_sync(0xffffffffu, clsum, o);
        dsum  += __shfl_down_sync(0xffffffffu, dsum,  o);
    }
    int warp = tid >> 5, lane = tid & 31;
    if (lane == 0) { s_red[warp] = (double)clsum; s_red[8 + warp] = (double)dsum; }
    __syncthreads();
    if (tid == 0) {
        double tc = 0.0, td = 0.0;
        #pragma unroll
        for (int w = 0; w < 8; w++) { tc += s_red[w]; td += s_red[8 + w]; }
        atomicAdd(&g_acc[0], tc);
        atomicAdd(&g_acc[1], td);
    }
}

// ---------------- kernel 3: finalize scalars ----------------
__global__ void k_final(float* __restrict__ out) {
    if (threadIdx.x == 0) {
        out[OUT_DATA_ELEMS + 0] = (float)(g_acc[0] / (double)BN);                     // cluster_loss
        out[OUT_DATA_ELEMS + 1] = (float)(g_acc[1] / ((double)BN * PK * PK));         // dist_mat.mean
        out[OUT_DATA_ELEMS + 2] = (float)(g_acc[2] / ((double)BN * S_OUT));           // wh.mean
    }
}

// ---------------- launch ----------------
extern "C" void kernel_launch(void* const* d_in, const int* in_sizes, int n_in,
                              void* d_out, int out_size)
{
    // metadata order: 0 fushed_features (unused), 1 input_data, 2 w_W, 3 w_b,
    //                 4 a1_W, 5 a1_b, 6 a2_W, 7 a2_b, 8 adj_mx_topk_index
    const float* input_data = (const float*)d_in[1];
    const float* wW  = (const float*)d_in[2];
    const float* wb  = (const float*)d_in[3];
    const float* a1W = (const float*)d_in[4];
    const float* a1b = (const float*)d_in[5];
    const float* a2W = (const float*)d_in[6];
    const float* a2b = (const float*)d_in[7];
    const int*   idx = (const int*)d_in[8];
    float* out = (float*)d_out;

    k_init<<<1, 32>>>();
    k_pre<<<(BN + 127) / 128, 128>>>(input_data, wW, wb, a1W, a1b);
    k_main<<<BN, 256>>>(idx, a2W, a2b, out);
    k_final<<<1, 32>>>(out);
}

// round 8
// speedup vs baseline: 1.5296x; 1.5296x over previous
#include <cuda_runtime.h>
#include <math.h>

// Problem constants
#define PB     32
#define PN     325
#define PK     20
#define S_IN   12
#define S_OUT  12
#define PC     10
#define H48    48
#define BN     (PB * PN)                 // 10400 nodes
#define OUT_DATA_ELEMS (BN * PC * S_OUT) // 1,248,000
#define WARPS  8                         // nodes per CTA in k_main
#define MAIN_BLOCKS (BN / WARPS)         // 1300 (exact)

// ---------------- scratch (no allocation allowed) ----------------
__device__ __align__(16) float  g_wh [BN * S_OUT];   // wh per node (12)
__device__ __align__(16) float  g_hxb[BN * H48];     // hx + a1_b per node (48)
__device__ __align__(16) float  g_hy [BN * H48];     // hy per node (48)
__device__ double g_acc[3];        // 0: cluster-loss sum, 1: dist sum, 2: wh sum
__device__ unsigned int g_done;    // last-block counter (self-resetting)

__device__ __forceinline__ float leaky(float x) { return x >= 0.f ? x : 0.5f * x; }

// ---------------- kernel 1: per-node precompute ----------------
// wh = leaky(x @ w_W + w_b); hxb = wh @ a1_W[:12] + a1_b; hy = wh @ a1_W[12:]
// Also accumulates sum(wh) into g_acc[2] (g_acc was reset by previous run's k_main).
__global__ void __launch_bounds__(128)
k_pre(const float* __restrict__ in,
      const float* __restrict__ wW,  const float* __restrict__ wb,
      const float* __restrict__ a1W, const float* __restrict__ a1b)
{
    __shared__ float s_wW[S_IN * S_OUT];
    __shared__ float s_wb[S_OUT];
    __shared__ float s_a1W[2 * S_OUT * H48];
    __shared__ float s_a1b[H48];
    __shared__ double s_red[4];

    for (int i = threadIdx.x; i < S_IN * S_OUT;    i += blockDim.x) s_wW[i]  = wW[i];
    for (int i = threadIdx.x; i < S_OUT;           i += blockDim.x) s_wb[i]  = wb[i];
    for (int i = threadIdx.x; i < 2 * S_OUT * H48; i += blockDim.x) s_a1W[i] = a1W[i];
    for (int i = threadIdx.x; i < H48;             i += blockDim.x) s_a1b[i] = a1b[i];
    __syncthreads();

    int node = blockIdx.x * blockDim.x + threadIdx.x;
    float whsum = 0.f;
    if (node < BN) {
        float x[S_IN];
        #pragma unroll
        for (int i = 0; i < S_IN; i++) x[i] = in[node * S_IN + i];

        float wh[S_OUT];
        #pragma unroll
        for (int j = 0; j < S_OUT; j++) {
            float a = s_wb[j];
            #pragma unroll
            for (int i = 0; i < S_IN; i++) a = fmaf(x[i], s_wW[i * S_OUT + j], a);
            wh[j] = leaky(a);
            whsum += wh[j];
            g_wh[node * S_OUT + j] = wh[j];
        }
        #pragma unroll
        for (int d = 0; d < H48; d++) {
            float hx = s_a1b[d];
            float hy = 0.f;
            #pragma unroll
            for (int j = 0; j < S_OUT; j++) {
                hx = fmaf(wh[j], s_a1W[j * H48 + d], hx);
                hy = fmaf(wh[j], s_a1W[(S_OUT + j) * H48 + d], hy);
            }
            g_hxb[node * H48 + d] = hx;
            g_hy [node * H48 + d] = hy;
        }
    }

    #pragma unroll
    for (int o = 16; o > 0; o >>= 1) whsum += __shfl_down_sync(0xffffffffu, whsum, o);
    int warp = threadIdx.x >> 5, lane = threadIdx.x & 31;
    if (lane == 0) s_red[warp] = (double)whsum;
    __syncthreads();
    if (threadIdx.x == 0) {
        double t = s_red[0] + s_red[1] + s_red[2] + s_red[3];
        atomicAdd(&g_acc[2], t);
    }
}

// ---------------- kernel 2: warp-per-node main + fused finalize ----------------
struct WarpSmem {
    float hxa[H48];          // own hx + a1_b
    float am [PK][11];       // softmaxed attention (padded: gcd(11,32)=1)
    float whk[PK][13];       // gathered wh (padded: gcd(13,32)=1)
    float inv[PK];           // 1/(||wh_k||+1e-8)
    int   j  [PK];
};

__global__ void __launch_bounds__(32 * WARPS)
k_main(const int* __restrict__ idx,
       const float* __restrict__ a2W, const float* __restrict__ a2b,
       float* __restrict__ out)
{
    __shared__ WarpSmem ws[WARPS];
    __shared__ float s_w2[H48 * PC];   // 480
    __shared__ float s_b2[PC];
    __shared__ double s_red[2 * WARPS];

    const int tid  = threadIdx.x;
    const int wid  = tid >> 5;
    const int lane = tid & 31;
    const int node = blockIdx.x * WARPS + wid;   // < BN always (1300*8 = 10400)
    const int base = (node / PN) * PN;           // batch row base
    WarpSmem* w = &ws[wid];

    for (int i = tid; i < H48 * PC; i += blockDim.x) s_w2[i] = a2W[i];
    if (tid < PC) s_b2[tid] = a2b[tid];
    __syncthreads();

    // ---- stage own hxa and neighbor indices ----
    if (lane < 12) {
        float4 t = reinterpret_cast<const float4*>(&g_hxb[(size_t)node * H48])[lane];
        w->hxa[lane * 4 + 0] = t.x; w->hxa[lane * 4 + 1] = t.y;
        w->hxa[lane * 4 + 2] = t.z; w->hxa[lane * 4 + 3] = t.w;
    }
    if (lane < PK) w->j[lane] = idx[node * PK + lane];
    __syncwarp();

    // ---- lane k: attention logits -> softmax; gather wh_k ----
    if (lane < PK) {
        int jn = base + w->j[lane];

        // hy gather: 12 independent LDG.128 (front-batched)
        float4 v[12];
        const float4* hyp = reinterpret_cast<const float4*>(&g_hy[(size_t)jn * H48]);
        #pragma unroll
        for (int i = 0; i < 12; i++) v[i] = hyp[i];

        float acc[PC];
        #pragma unroll
        for (int c = 0; c < PC; c++) acc[c] = s_b2[c];

        #pragma unroll
        for (int i = 0; i < 12; i++) {
            float hv[4] = {v[i].x, v[i].y, v[i].z, v[i].w};
            #pragma unroll
            for (int q = 0; q < 4; q++) {
                int d = i * 4 + q;
                float h = leaky(w->hxa[d] + hv[q]);   // computed once, reused for 10 c's
                #pragma unroll
                for (int c = 0; c < PC; c++) acc[c] = fmaf(h, s_w2[d * PC + c], acc[c]);
            }
        }
        // leaky + softmax (in-lane)
        float m = -1e30f;
        #pragma unroll
        for (int c = 0; c < PC; c++) { acc[c] = leaky(acc[c]); m = fmaxf(m, acc[c]); }
        float sum = 0.f;
        #pragma unroll
        for (int c = 0; c < PC; c++) { acc[c] = __expf(acc[c] - m); sum += acc[c]; }
        float is = 1.f / sum;
        #pragma unroll
        for (int c = 0; c < PC; c++) w->am[lane][c] = acc[c] * is;

        // gather wh_k, inv-norm
        const float4* wp = reinterpret_cast<const float4*>(&g_wh[(size_t)jn * S_OUT]);
        float4 a = wp[0], b = wp[1], cc = wp[2];
        float wr[12] = {a.x, a.y, a.z, a.w, b.x, b.y, b.z, b.w, cc.x, cc.y, cc.z, cc.w};
        float n2 = 0.f;
        #pragma unroll
        for (int s = 0; s < S_OUT; s++) { n2 = fmaf(wr[s], wr[s], n2); w->whk[lane][s] = wr[s]; }
        w->inv[lane] = 1.f / (sqrtf(n2) + 1e-8f);
    }
    __syncwarp();

    // ---- output: out[node, c, s] = sum_k am[k][c] * whk[k][s] ----
    #pragma unroll
    for (int i = lane; i < PC * S_OUT; i += 32) {
        int c = i / S_OUT, s = i - c * S_OUT;
        float o = 0.f;
        #pragma unroll
        for (int k = 0; k < PK; k++) o = fmaf(w->am[k][c], w->whk[k][s], o);
        out[(size_t)node * (PC * S_OUT) + i] = o;
    }

    // ---- K x K pair phase ----
    float clsum = 0.f, dsum = 0.f;
    for (int p = lane; p < PK * PK; p += 32) {
        int k = p / PK, l = p - k * PK;
        float dot = 0.f;
        #pragma unroll
        for (int s = 0; s < S_OUT; s++) dot = fmaf(w->whk[k][s], w->whk[l][s], dot);
        float dist = dot * w->inv[k] * w->inv[l];
        dsum += dist;
        if (k != l) {
            float prob = 0.f;
            #pragma unroll
            for (int c = 0; c < PC; c++) prob = fmaf(w->am[k][c], w->am[l][c], prob);
            prob = fminf(fmaxf(prob, 1e-4f), 1.f - 1e-4f);
            float logp = __logf(prob);
            clsum += (dist >= 0.5f) ? -logp : logp;   // -(same*logp - diff*logp)
        }
    }

    // ---- reduce: warp -> block -> global atomics ----
    #pragma unroll
    for (int o = 16; o > 0; o >>= 1) {
        clsum += __shfl_down_sync(0xffffffffu, clsum, o);
        dsum  += __shfl_down_sync(0xffffffffu, dsum,  o);
    }
    if (lane == 0) { s_red[wid] = (double)clsum; s_red[WARPS + wid] = (double)dsum; }
    __syncthreads();

    if (tid == 0) {
        double tc = 0.0, td = 0.0;
        #pragma unroll
        for (int q = 0; q < WARPS; q++) { tc += s_red[q]; td += s_red[WARPS + q]; }
        atomicAdd(&g_acc[0], tc);
        atomicAdd(&g_acc[1], td);
        __threadfence();
        unsigned int done = atomicAdd(&g_done, 1u);
        if (done == (unsigned int)(gridDim.x - 1)) {
            // last CTA: finalize scalars, then reset accumulators for next run
            __threadfence();
            volatile double* acc = g_acc;
            double c0 = acc[0], c1 = acc[1], c2 = acc[2];
            out[OUT_DATA_ELEMS + 0] = (float)(c0 / (double)BN);
            out[OUT_DATA_ELEMS + 1] = (float)(c1 / ((double)BN * PK * PK));
            out[OUT_DATA_ELEMS + 2] = (float)(c2 / ((double)BN * S_OUT));
            acc[0] = 0.0; acc[1] = 0.0; acc[2] = 0.0;
            g_done = 0;
            __threadfence();
        }
    }
}

// ---------------- launch ----------------
extern "C" void kernel_launch(void* const* d_in, const int* in_sizes, int n_in,
                              void* d_out, int out_size)
{
    // metadata order: 0 fushed_features (unused), 1 input_data, 2 w_W, 3 w_b,
    //                 4 a1_W, 5 a1_b, 6 a2_W, 7 a2_b, 8 adj_mx_topk_index
    const float* input_data = (const float*)d_in[1];
    const float* wW  = (const float*)d_in[2];
    const float* wb  = (const float*)d_in[3];
    const float* a1W = (const float*)d_in[4];
    const float* a1b = (const float*)d_in[5];
    const float* a2W = (const float*)d_in[6];
    const float* a2b = (const float*)d_in[7];
    const int*   idx = (const int*)d_in[8];
    float* out = (float*)d_out;

    k_pre <<<(BN + 127) / 128, 128>>>(input_data, wW, wb, a1W, a1b);
    k_main<<<MAIN_BLOCKS, 32 * WARPS>>>(idx, a2W, a2b, out);
}